// round 2
// baseline (speedup 1.0000x reference)
#include <cuda_runtime.h>

#define B_DIM 8
#define C_DIM 4
#define T_DIM 262144
#define T4 (T_DIM / 4)
#define GRID_X 64
#define NTHREADS 256
#define TOTAL_BLOCKS (GRID_X * B_DIM)

// Scratch: per-batch 4x4 distance partial sums (i = y channel, j = x channel)
// Zero-initialized at module load; last block resets to 0 after each call,
// so every graph replay sees a clean slate (deterministic, allocation-free).
__device__ float g_partial[B_DIM][16];
__device__ unsigned int g_ticket;  // zero-init; reset by last block

__global__ void __launch_bounds__(NTHREADS) pit_fused_kernel(
    const float* __restrict__ x, const float* __restrict__ y,
    float* __restrict__ out) {
    const int b = blockIdx.y;
    const float4* __restrict__ x4 =
        (const float4*)(x + (long long)b * C_DIM * T_DIM);
    const float4* __restrict__ y4 =
        (const float4*)(y + (long long)b * C_DIM * T_DIM);

    float acc[16];
#pragma unroll
    for (int k = 0; k < 16; k++) acc[k] = 0.0f;

    // T4 = 65536, GRID_X*NTHREADS = 16384 -> exactly 4 iterations per thread
    const int base = blockIdx.x * NTHREADS + threadIdx.x;
#pragma unroll
    for (int it = 0; it < 4; it++) {
        const int idx = base + it * (GRID_X * NTHREADS);
        float4 xv[C_DIM], yv[C_DIM];
#pragma unroll
        for (int c = 0; c < C_DIM; c++) {
            xv[c] = x4[c * T4 + idx];
            yv[c] = y4[c * T4 + idx];
        }
#pragma unroll
        for (int i = 0; i < C_DIM; i++) {
#pragma unroll
            for (int j = 0; j < C_DIM; j++) {
                float d0 = xv[j].x - yv[i].x;
                float d1 = xv[j].y - yv[i].y;
                float d2 = xv[j].z - yv[i].z;
                float d3 = xv[j].w - yv[i].w;
                acc[i * 4 + j] += d0 * d0 + d1 * d1 + d2 * d2 + d3 * d3;
            }
        }
    }

    // Warp reduction for each of the 16 accumulators
#pragma unroll
    for (int k = 0; k < 16; k++) {
#pragma unroll
        for (int off = 16; off > 0; off >>= 1)
            acc[k] += __shfl_down_sync(0xffffffff, acc[k], off);
    }

    __shared__ float s_acc[16];
    if (threadIdx.x < 16) s_acc[threadIdx.x] = 0.0f;
    __syncthreads();
    if ((threadIdx.x & 31) == 0) {
#pragma unroll
        for (int k = 0; k < 16; k++) atomicAdd(&s_acc[k], acc[k]);
    }
    __syncthreads();
    if (threadIdx.x < 16) atomicAdd(&g_partial[b][threadIdx.x], s_acc[threadIdx.x]);

    // ---- last-block-done finalize (single launch, no extra kernels) ----
    __shared__ bool s_is_last;
    __threadfence();
    if (threadIdx.x == 0) {
        unsigned int t = atomicAdd(&g_ticket, 1u);
        s_is_last = (t == TOTAL_BLOCKS - 1);
    }
    __syncthreads();
    if (!s_is_last) return;

    // Load all 128 partials in parallel (L2-coherent loads; atomics landed in L2)
    __shared__ float s_d[B_DIM * 16];
    if (threadIdx.x < B_DIM * 16)
        s_d[threadIdx.x] = __ldcg(&((const float*)g_partial)[threadIdx.x]);
    __syncthreads();

    if (threadIdx.x == 0) {
        const float inv_t = 1.0f / (float)T_DIM;
        float total = 0.0f;
        for (int bb = 0; bb < B_DIM; bb++) {
            const float* d = &s_d[bb * 16];
            float best = 3.4e38f;
            for (int p0 = 0; p0 < 4; p0++)
                for (int p1 = 0; p1 < 4; p1++) {
                    if (p1 == p0) continue;
                    for (int p2 = 0; p2 < 4; p2++) {
                        if (p2 == p0 || p2 == p1) continue;
                        int p3 = 6 - p0 - p1 - p2;
                        float c = d[0 * 4 + p0] + d[1 * 4 + p1] +
                                  d[2 * 4 + p2] + d[3 * 4 + p3];
                        best = fminf(best, c);
                    }
                }
            total += best * inv_t;
        }
        out[0] = total;
        g_ticket = 0;  // reset for next replay
    }
    // Reset scratch for next replay
    if (threadIdx.x < B_DIM * 16)
        ((float*)g_partial)[threadIdx.x] = 0.0f;
}

extern "C" void kernel_launch(void* const* d_in, const int* in_sizes, int n_in,
                              void* d_out, int out_size) {
    const float* x = (const float*)d_in[0];
    const float* y = (const float*)d_in[1];
    float* out = (float*)d_out;

    dim3 grid(GRID_X, B_DIM);
    pit_fused_kernel<<<grid, NTHREADS>>>(x, y, out);
}